// round 3
// baseline (speedup 1.0000x reference)
#include <cuda_runtime.h>
#include <cstdint>

// Shapes (fixed by the problem)
#define B_    64
#define S_    16
#define J_    256
#define QDIM_ 512
#define IDIM_ 512
#define HDIM_ 256
#define BS_   (B_ * S_)    // 1024
#define CHK_  16           // rows per staged chunk
#define NCHK_ (J_ / CHK_)  // 16 chunks

// Scratch (allocation-free rule: __device__ globals)
__device__ float g_qt[B_ * IDIM_];        // scale * Wk^T (Wq q)  [64, 512]
__device__ float g_pooled[BS_ * IDIM_];   // softmax-pooled inputs [1024, 512]
__device__ float g_WvT[IDIM_ * HDIM_];    // Wv transposed        [512, 256]
__device__ int   g_mask_u8;               // 1 = mask is u8 bool, 0 = int32

// ---------------------------------------------------------------------------
// Kernel 0: detect mask dtype (int32 {0,1} words vs packed 1-byte bools).
// Deterministic pure function of the input.
// ---------------------------------------------------------------------------
__global__ void detect_mask_kernel(const unsigned* __restrict__ mask_words)
{
    __shared__ int any_gt1;
    if (threadIdx.x == 0) any_gt1 = 0;
    __syncthreads();
    int local = 0;
    for (int i = threadIdx.x; i < 1024; i += blockDim.x)
        if (mask_words[i] > 1u) local = 1;
    if (local) any_gt1 = 1;
    __syncthreads();
    if (threadIdx.x == 0) g_mask_u8 = any_gt1;
}

// ---------------------------------------------------------------------------
// Kernel 0b: WvT[i, h] = Wv[h, i]   (standard 32x32 smem transpose)
// grid = (IDIM/32, HDIM/32) = (16, 8), block = (32, 8)
// ---------------------------------------------------------------------------
__global__ void transpose_wv_kernel(const float* __restrict__ Wv)
{
    __shared__ float tile[32][33];
    const int i0 = blockIdx.x * 32;   // IDIM tile
    const int h0 = blockIdx.y * 32;   // HDIM tile
    #pragma unroll
    for (int r = 0; r < 32; r += 8) {
        int h = h0 + threadIdx.y + r;
        tile[threadIdx.y + r][threadIdx.x] = Wv[(size_t)h * IDIM_ + i0 + threadIdx.x];
    }
    __syncthreads();
    #pragma unroll
    for (int r = 0; r < 32; r += 8) {
        int i = i0 + threadIdx.y + r;
        g_WvT[(size_t)i * HDIM_ + h0 + threadIdx.x] = tile[threadIdx.x][threadIdx.y + r];
    }
}

// ---------------------------------------------------------------------------
// Kernel 1: q̃_b = scale * (Wk^T (Wq query_b)); grid = 64, 256 threads
// ---------------------------------------------------------------------------
__global__ __launch_bounds__(256) void qt_kernel(
    const float* __restrict__ query,  // [64, 512]
    const float* __restrict__ Wq,     // [256, 512]
    const float* __restrict__ Wk)     // [256, 512]
{
    const int b   = blockIdx.x;
    const int tid = threadIdx.x;

    __shared__ float sq[QDIM_];
    __shared__ float sQ[HDIM_];

    sq[tid]       = query[b * QDIM_ + tid];
    sq[tid + 256] = query[b * QDIM_ + tid + 256];
    __syncthreads();

    {   // Q[b,h], thread = h (row of Wq streams coalesced within thread)
        const float4* wq = reinterpret_cast<const float4*>(Wq + (size_t)tid * QDIM_);
        const float4* q4 = reinterpret_cast<const float4*>(sq);
        float acc = 0.f;
        #pragma unroll 8
        for (int k = 0; k < QDIM_ / 4; ++k) {
            float4 w = wq[k], q = q4[k];
            acc = fmaf(w.x, q.x, acc);
            acc = fmaf(w.y, q.y, acc);
            acc = fmaf(w.z, q.z, acc);
            acc = fmaf(w.w, q.w, acc);
        }
        sQ[tid] = acc;
    }
    __syncthreads();

    const float scale = 0.0625f;  // 1/sqrt(HDIM=256)
    for (int i = tid; i < IDIM_; i += 256) {
        float acc = 0.f;
        #pragma unroll 4
        for (int h = 0; h < HDIM_; ++h)
            acc = fmaf(sQ[h], Wk[(size_t)h * IDIM_ + i], acc);
        g_qt[b * IDIM_ + i] = acc * scale;
    }
}

// ---------------------------------------------------------------------------
// Kernel 2: chunked flash softmax-pooling. One block per (b,s), 256 threads.
// 16-row chunks double-buffered in SMEM; softmax coefs computed once per
// chunk by warp 0 and broadcast; accumulation is 2 cols/thread streaming.
// ---------------------------------------------------------------------------
__global__ __launch_bounds__(256) void flash_pool_kernel(
    const float* __restrict__ X,     // [64,16,256,512]
    const void*  __restrict__ mask)  // [64,16,256] u8 or i32 (detected)
{
    const int bs   = blockIdx.x;
    const int b    = bs >> 4;
    const int tid  = threadIdx.x;
    const int wid  = tid >> 5;
    const int lane = tid & 31;

    __shared__ float4 s_stage[2][CHK_ * 128];  // 2 x 32 KB
    __shared__ float  s_score[CHK_];
    __shared__ float  s_w[CHK_];
    __shared__ float  s_coef[3];               // f, wsum, M_new

    const float4* x4 = reinterpret_cast<const float4*>(X + (size_t)bs * J_ * IDIM_);
    const int mask_is_u8 = g_mask_u8;
    const uint8_t* mk8  = (const uint8_t*)mask + (size_t)bs * J_;
    const int*     mk32 = (const int*)mask + (size_t)bs * J_;

    // Lane-resident q-tilde slice (read through L2; broadcast-friendly)
    float4 qv[4];
    {
        const float4* q4 = reinterpret_cast<const float4*>(g_qt + b * IDIM_);
        #pragma unroll
        for (int k = 0; k < 4; ++k) qv[k] = q4[lane + 32 * k];
    }

    // Preload chunk 0 (8 float4 per thread = 2048 float4 = 16 rows)
    float4 ld[8];
    #pragma unroll
    for (int u = 0; u < 8; ++u) ld[u] = x4[tid + 256 * u];
    #pragma unroll
    for (int u = 0; u < 8; ++u) s_stage[0][tid + 256 * u] = ld[u];
    __syncthreads();

    float m = -1e30f, d = 0.f;
    float px = 0.f, py = 0.f;   // this thread's 2 pooled columns

    for (int c = 0; c < NCHK_; ++c) {
        const int cur = c & 1;

        // Prefetch next chunk into registers (overlaps with compute below)
        if (c < NCHK_ - 1) {
            const int base = (c + 1) * (CHK_ * 128);
            #pragma unroll
            for (int u = 0; u < 8; ++u) ld[u] = x4[base + tid + 256 * u];
        }

        // Scores: warp w computes rows 2w and 2w+1 (interleaved reductions)
        {
            const float4* r0 = &s_stage[cur][(2 * wid) * 128];
            const float4* r1 = r0 + 128;
            float s0 = 0.f, s1 = 0.f;
            #pragma unroll
            for (int k = 0; k < 4; ++k) {
                float4 a = r0[lane + 32 * k];
                float4 bb = r1[lane + 32 * k];
                s0 = fmaf(a.x, qv[k].x, s0);  s1 = fmaf(bb.x, qv[k].x, s1);
                s0 = fmaf(a.y, qv[k].y, s0);  s1 = fmaf(bb.y, qv[k].y, s1);
                s0 = fmaf(a.z, qv[k].z, s0);  s1 = fmaf(bb.z, qv[k].z, s1);
                s0 = fmaf(a.w, qv[k].w, s0);  s1 = fmaf(bb.w, qv[k].w, s1);
            }
            #pragma unroll
            for (int off = 16; off > 0; off >>= 1) {
                s0 += __shfl_xor_sync(0xffffffffu, s0, off);
                s1 += __shfl_xor_sync(0xffffffffu, s1, off);
            }
            if (lane == 0) {
                s_score[2 * wid]     = s0;
                s_score[2 * wid + 1] = s1;
            }
        }
        __syncthreads();

        // Warp 0: chunk softmax coefficients (one exp per row + one rescale)
        if (wid == 0) {
            float sc = -1e30f;
            if (lane < CHK_) {
                sc = s_score[lane];
                const int j = c * CHK_ + lane;
                const bool msk = mask_is_u8 ? (mk8[j] != 0) : (mk32[j] != 0);
                if (msk) sc = -1e30f;
            }
            float mx = sc;
            #pragma unroll
            for (int off = 16; off > 0; off >>= 1)
                mx = fmaxf(mx, __shfl_xor_sync(0xffffffffu, mx, off));
            const float Mn = fmaxf(m, mx);
            const float w  = (lane < CHK_) ? __expf(sc - Mn) : 0.f;
            float ws = w;
            #pragma unroll
            for (int off = 16; off > 0; off >>= 1)
                ws += __shfl_xor_sync(0xffffffffu, ws, off);
            if (lane < CHK_) s_w[lane] = w;
            if (lane == 0) {
                s_coef[0] = __expf(m - Mn);
                s_coef[1] = ws;
                s_coef[2] = Mn;
            }
        }
        __syncthreads();

        const float f  = s_coef[0];
        const float ws = s_coef[1];
        m = s_coef[2];
        d = fmaf(d, f, ws);

        // Accumulate: thread owns cols {2*tid, 2*tid+1}
        px *= f;  py *= f;
        const float2* st2 = reinterpret_cast<const float2*>(&s_stage[cur][0]);
        #pragma unroll
        for (int r = 0; r < CHK_; ++r) {
            const float  wr = s_w[r];
            const float2 xv = st2[r * 256 + tid];
            px = fmaf(wr, xv.x, px);
            py = fmaf(wr, xv.y, py);
        }

        // Commit prefetched chunk to the other buffer
        if (c < NCHK_ - 1) {
            #pragma unroll
            for (int u = 0; u < 8; ++u) s_stage[cur ^ 1][tid + 256 * u] = ld[u];
        }
        __syncthreads();
    }

    const float inv = 1.f / d;
    float2 outp; outp.x = px * inv; outp.y = py * inv;
    reinterpret_cast<float2*>(g_pooled + (size_t)bs * IDIM_)[tid] = outp;
}

// ---------------------------------------------------------------------------
// Kernel 3: out[m, h] = sum_i pooled[m, i] * WvT[i, h]
// grid = 128 (8 m-rows each), 256 threads (thread = h, fully coalesced).
// ---------------------------------------------------------------------------
#define MT_ 8
__global__ __launch_bounds__(256) void epilogue_kernel(float* __restrict__ out)
{
    const int m0  = blockIdx.x * MT_;
    const int tid = threadIdx.x;

    __shared__ float sP[MT_][IDIM_];   // 16 KB
    for (int idx = tid; idx < MT_ * IDIM_; idx += 256)
        sP[idx >> 9][idx & 511] = g_pooled[(size_t)(m0 + (idx >> 9)) * IDIM_ + (idx & 511)];
    __syncthreads();

    const int h = tid;
    float acc[MT_];
    #pragma unroll
    for (int mm = 0; mm < MT_; ++mm) acc[mm] = 0.f;

    // i-loop: WvT[i*256 + h] is coalesced across threads; unroll 4 for MLP
    #pragma unroll 4
    for (int i = 0; i < IDIM_; ++i) {
        const float wv = g_WvT[(size_t)i * HDIM_ + h];
        #pragma unroll
        for (int mm = 0; mm < MT_; ++mm)
            acc[mm] = fmaf(wv, sP[mm][i], acc[mm]);
    }
    #pragma unroll
    for (int mm = 0; mm < MT_; ++mm)
        out[(size_t)(m0 + mm) * HDIM_ + h] = acc[mm];
}

// ---------------------------------------------------------------------------
// Launch.  Inputs: query, other_semesters, mask, Wq, Wk, Wv
// ---------------------------------------------------------------------------
extern "C" void kernel_launch(void* const* d_in, const int* in_sizes, int n_in,
                              void* d_out, int out_size)
{
    const float* query = (const float*)d_in[0];
    const float* X     = (const float*)d_in[1];
    const void*  mask  = d_in[2];
    const float* Wq    = (const float*)d_in[3];
    const float* Wk    = (const float*)d_in[4];
    const float* Wv    = (const float*)d_in[5];
    float*       out   = (float*)d_out;

    detect_mask_kernel<<<1, 256>>>((const unsigned*)mask);
    transpose_wv_kernel<<<dim3(IDIM_ / 32, HDIM_ / 32), dim3(32, 8)>>>(Wv);
    qt_kernel<<<B_, 256>>>(query, Wq, Wk);
    flash_pool_kernel<<<BS_, 256>>>(X, mask);
    epilogue_kernel<<<BS_ / MT_, 256>>>(out);
}

// round 4
// speedup vs baseline: 1.0736x; 1.0736x over previous
#include <cuda_runtime.h>
#include <cstdint>

// Shapes (fixed)
#define B_    64
#define S_    16
#define J_    256
#define QDIM_ 512
#define IDIM_ 512
#define HDIM_ 256
#define BS_   (B_ * S_)    // 1024
#define CHK_  16           // rows per staged chunk
#define NCHK_ (J_ / CHK_)  // 16 chunks

// Scratch (__device__ globals: allocation-free rule)
__device__ float g_qt[B_ * IDIM_];        // scale * Wk^T (Wq q)   [64, 512]
__device__ float g_pooled[BS_ * IDIM_];   // softmax-pooled inputs [1024, 512]
__device__ float g_WvT[IDIM_ * HDIM_];    // Wv transposed         [512, 256]
__device__ int   g_mask_u8;               // 1 = u8 bool mask, 0 = int32

// ---------------- cp.async helpers ----------------
__device__ __forceinline__ void cp_async16(unsigned dst_smem, const void* src) {
    asm volatile("cp.async.cg.shared.global [%0], [%1], 16;"
                 :: "r"(dst_smem), "l"(src));
}
__device__ __forceinline__ void cp_commit() {
    asm volatile("cp.async.commit_group;");
}
__device__ __forceinline__ void cp_wait_all() {
    asm volatile("cp.async.wait_group 0;");
}

// ---------------------------------------------------------------------------
// Kernel 0: detect mask dtype (int32 {0,1} words vs packed 1-byte bools).
// ---------------------------------------------------------------------------
__global__ void detect_mask_kernel(const unsigned* __restrict__ mask_words)
{
    __shared__ int any_gt1;
    if (threadIdx.x == 0) any_gt1 = 0;
    __syncthreads();
    int local = 0;
    for (int i = threadIdx.x; i < 1024; i += blockDim.x)
        if (mask_words[i] > 1u) local = 1;
    if (local) any_gt1 = 1;
    __syncthreads();
    if (threadIdx.x == 0) g_mask_u8 = any_gt1;
}

// ---------------------------------------------------------------------------
// Kernel 0b: WvT[i, h] = Wv[h, i]
// ---------------------------------------------------------------------------
__global__ void transpose_wv_kernel(const float* __restrict__ Wv)
{
    __shared__ float tile[32][33];
    const int i0 = blockIdx.x * 32;
    const int h0 = blockIdx.y * 32;
    #pragma unroll
    for (int r = 0; r < 32; r += 8)
        tile[threadIdx.y + r][threadIdx.x] =
            Wv[(size_t)(h0 + threadIdx.y + r) * IDIM_ + i0 + threadIdx.x];
    __syncthreads();
    #pragma unroll
    for (int r = 0; r < 32; r += 8)
        g_WvT[(size_t)(i0 + threadIdx.y + r) * HDIM_ + h0 + threadIdx.x] =
            tile[threadIdx.x][threadIdx.y + r];
}

// ---------------------------------------------------------------------------
// Kernel 1: q̃_b = scale * (Wk^T (Wq query_b)); grid = 64, 256 threads
// ---------------------------------------------------------------------------
__global__ __launch_bounds__(256) void qt_kernel(
    const float* __restrict__ query,  // [64, 512]
    const float* __restrict__ Wq,     // [256, 512]
    const float* __restrict__ Wk)     // [256, 512]
{
    const int b   = blockIdx.x;
    const int tid = threadIdx.x;

    __shared__ float sq[QDIM_];
    __shared__ float sQ[HDIM_];

    sq[tid]       = query[b * QDIM_ + tid];
    sq[tid + 256] = query[b * QDIM_ + tid + 256];
    __syncthreads();

    {   // Q[b,h], thread = h
        const float4* wq = reinterpret_cast<const float4*>(Wq + (size_t)tid * QDIM_);
        const float4* q4 = reinterpret_cast<const float4*>(sq);
        float a0 = 0.f, a1 = 0.f;
        #pragma unroll 8
        for (int k = 0; k < QDIM_ / 4; k += 2) {
            float4 w = wq[k],     q = q4[k];
            float4 w2 = wq[k+1],  q2 = q4[k+1];
            a0 = fmaf(w.x, q.x, a0);  a0 = fmaf(w.y, q.y, a0);
            a0 = fmaf(w.z, q.z, a0);  a0 = fmaf(w.w, q.w, a0);
            a1 = fmaf(w2.x, q2.x, a1); a1 = fmaf(w2.y, q2.y, a1);
            a1 = fmaf(w2.z, q2.z, a1); a1 = fmaf(w2.w, q2.w, a1);
        }
        sQ[tid] = a0 + a1;
    }
    __syncthreads();

    // qt[b,i]: 4 independent accumulators, unroll -> ~16 loads in flight
    const float scale = 0.0625f;  // 1/sqrt(256)
    for (int i = tid; i < IDIM_; i += 256) {
        float a0 = 0.f, a1 = 0.f, a2 = 0.f, a3 = 0.f;
        #pragma unroll 4
        for (int h = 0; h < HDIM_; h += 4) {
            a0 = fmaf(sQ[h + 0], Wk[(size_t)(h + 0) * IDIM_ + i], a0);
            a1 = fmaf(sQ[h + 1], Wk[(size_t)(h + 1) * IDIM_ + i], a1);
            a2 = fmaf(sQ[h + 2], Wk[(size_t)(h + 2) * IDIM_ + i], a2);
            a3 = fmaf(sQ[h + 3], Wk[(size_t)(h + 3) * IDIM_ + i], a3);
        }
        g_qt[b * IDIM_ + i] = ((a0 + a1) + (a2 + a3)) * scale;
    }
}

// ---------------------------------------------------------------------------
// Kernel 2: chunked flash softmax-pooling, cp.async double-buffered.
// One block per (b,s), 256 threads; 2 barriers/chunk; softmax coefs
// computed redundantly per-warp (no warp-0 serialization, no extra barrier).
// ---------------------------------------------------------------------------
__global__ __launch_bounds__(256) void flash_pool_kernel(
    const float* __restrict__ X,     // [64,16,256,512]
    const void*  __restrict__ mask)  // [64,16,256] u8 or i32
{
    const int bs   = blockIdx.x;
    const int b    = bs >> 4;
    const int tid  = threadIdx.x;
    const int wid  = tid >> 5;
    const int lane = tid & 31;

    __shared__ float4 s_stage[2][CHK_ * 128];  // 2 x 32 KB
    __shared__ float  s_score[CHK_];

    const float4* x4 = reinterpret_cast<const float4*>(X + (size_t)bs * J_ * IDIM_);
    const int mask_is_u8 = g_mask_u8;
    const uint8_t* mk8  = (const uint8_t*)mask + (size_t)bs * J_;
    const int*     mk32 = (const int*)mask + (size_t)bs * J_;

    // Lane-resident q-tilde slice
    float4 qv[4];
    {
        const float4* q4 = reinterpret_cast<const float4*>(g_qt + b * IDIM_);
        #pragma unroll
        for (int k = 0; k < 4; ++k) qv[k] = q4[lane + 32 * k];
    }

    const unsigned sbuf[2] = {
        (unsigned)__cvta_generic_to_shared(&s_stage[0][0]),
        (unsigned)__cvta_generic_to_shared(&s_stage[1][0])
    };

    // Kick off chunk 0 copy
    #pragma unroll
    for (int u = 0; u < 8; ++u)
        cp_async16(sbuf[0] + (unsigned)(tid + 256 * u) * 16u, x4 + tid + 256 * u);
    cp_commit();

    float m = -1e30f, d = 0.f;
    float px = 0.f, py = 0.f;

    for (int c = 0; c < NCHK_; ++c) {
        const int cur = c & 1;

        cp_wait_all();       // chunk c landed
        __syncthreads();     // ...visible to all; prev chunk fully consumed

        // Issue copy for chunk c+1 into the other buffer (now free)
        if (c < NCHK_ - 1) {
            const unsigned sb = sbuf[cur ^ 1];
            const float4* src = x4 + (size_t)(c + 1) * (CHK_ * 128);
            #pragma unroll
            for (int u = 0; u < 8; ++u)
                cp_async16(sb + (unsigned)(tid + 256 * u) * 16u, src + tid + 256 * u);
            cp_commit();
        }

        // Scores: warp w computes rows 2w, 2w+1
        {
            const float4* r0 = &s_stage[cur][(2 * wid) * 128];
            const float4* r1 = r0 + 128;
            float s0 = 0.f, s1 = 0.f;
            #pragma unroll
            for (int k = 0; k < 4; ++k) {
                float4 a  = r0[lane + 32 * k];
                float4 bb = r1[lane + 32 * k];
                s0 = fmaf(a.x,  qv[k].x, s0);  s1 = fmaf(bb.x, qv[k].x, s1);
                s0 = fmaf(a.y,  qv[k].y, s0);  s1 = fmaf(bb.y, qv[k].y, s1);
                s0 = fmaf(a.z,  qv[k].z, s0);  s1 = fmaf(bb.z, qv[k].z, s1);
                s0 = fmaf(a.w,  qv[k].w, s0);  s1 = fmaf(bb.w, qv[k].w, s1);
            }
            #pragma unroll
            for (int off = 16; off > 0; off >>= 1) {
                s0 += __shfl_xor_sync(0xffffffffu, s0, off);
                s1 += __shfl_xor_sync(0xffffffffu, s1, off);
            }
            if (lane == 0) {
                s_score[2 * wid]     = s0;
                s_score[2 * wid + 1] = s1;
            }
        }
        __syncthreads();

        // Every warp redundantly computes identical softmax coefficients
        float sc = -1e30f;
        if (lane < CHK_) {
            sc = s_score[lane];
            const int j = c * CHK_ + lane;
            const bool msk = mask_is_u8 ? (mk8[j] != 0) : (mk32[j] != 0);
            if (msk) sc = -1e30f;
        }
        float mx = sc;
        #pragma unroll
        for (int off = 16; off > 0; off >>= 1)
            mx = fmaxf(mx, __shfl_xor_sync(0xffffffffu, mx, off));
        const float Mn = fmaxf(m, mx);
        const float w  = (lane < CHK_) ? __expf(sc - Mn) : 0.f;
        float ws = w;
        #pragma unroll
        for (int off = 16; off > 0; off >>= 1)
            ws += __shfl_xor_sync(0xffffffffu, ws, off);
        const float f = __expf(m - Mn);
        m = Mn;
        d = fmaf(d, f, ws);

        // Accumulate: thread owns cols {2*tid, 2*tid+1}; w broadcast via shfl
        px *= f;  py *= f;
        const float2* st2 = reinterpret_cast<const float2*>(&s_stage[cur][0]);
        #pragma unroll
        for (int r = 0; r < CHK_; ++r) {
            const float  wr = __shfl_sync(0xffffffffu, w, r);
            const float2 xv = st2[r * 256 + tid];
            px = fmaf(wr, xv.x, px);
            py = fmaf(wr, xv.y, py);
        }
        // no trailing barrier: next iteration's top barrier orders buffer reuse
    }

    const float inv = 1.f / d;
    reinterpret_cast<float2*>(g_pooled + (size_t)bs * IDIM_)[tid] =
        make_float2(px * inv, py * inv);
}

// ---------------------------------------------------------------------------
// Kernel 3: out[m, h] = sum_i pooled[m, i] * WvT[i, h]
// grid = 128 (MT=8 rows each); 256 threads = 64 h-quads x 4 m-pairs.
// WvT loads are float4, coalesced; sP reads are warp-uniform broadcasts.
// ---------------------------------------------------------------------------
#define MT_ 8
__global__ __launch_bounds__(256) void epilogue_kernel(float* __restrict__ out)
{
    const int m0  = blockIdx.x * MT_;
    const int tid = threadIdx.x;
    const int hq  = tid & 63;    // h-quad: h = 4*hq .. 4*hq+3
    const int mg  = tid >> 6;    // m-pair: m = m0+2mg, m0+2mg+1

    __shared__ float sP[MT_][IDIM_];   // 16 KB
    {
        const float4* src = reinterpret_cast<const float4*>(g_pooled + (size_t)m0 * IDIM_);
        float4* dst = reinterpret_cast<float4*>(&sP[0][0]);
        #pragma unroll
        for (int u = 0; u < 4; ++u) dst[tid + 256 * u] = src[tid + 256 * u];
    }
    __syncthreads();

    const float4* wv4 = reinterpret_cast<const float4*>(g_WvT);
    const int mA = 2 * mg, mB = mA + 1;
    float4 a0 = make_float4(0.f, 0.f, 0.f, 0.f);
    float4 a1 = make_float4(0.f, 0.f, 0.f, 0.f);

    #pragma unroll 4
    for (int i = 0; i < IDIM_; ++i) {
        const float4 w  = __ldg(&wv4[i * 64 + hq]);
        const float  pA = sP[mA][i];
        const float  pB = sP[mB][i];
        a0.x = fmaf(w.x, pA, a0.x);  a0.y = fmaf(w.y, pA, a0.y);
        a0.z = fmaf(w.z, pA, a0.z);  a0.w = fmaf(w.w, pA, a0.w);
        a1.x = fmaf(w.x, pB, a1.x);  a1.y = fmaf(w.y, pB, a1.y);
        a1.z = fmaf(w.z, pB, a1.z);  a1.w = fmaf(w.w, pB, a1.w);
    }

    reinterpret_cast<float4*>(out + (size_t)(m0 + mA) * HDIM_)[hq] = a0;
    reinterpret_cast<float4*>(out + (size_t)(m0 + mB) * HDIM_)[hq] = a1;
}

// ---------------------------------------------------------------------------
// Launch.  Inputs: query, other_semesters, mask, Wq, Wk, Wv
// ---------------------------------------------------------------------------
extern "C" void kernel_launch(void* const* d_in, const int* in_sizes, int n_in,
                              void* d_out, int out_size)
{
    const float* query = (const float*)d_in[0];
    const float* X     = (const float*)d_in[1];
    const void*  mask  = d_in[2];
    const float* Wq    = (const float*)d_in[3];
    const float* Wk    = (const float*)d_in[4];
    const float* Wv    = (const float*)d_in[5];
    float*       out   = (float*)d_out;

    detect_mask_kernel<<<1, 256>>>((const unsigned*)mask);
    transpose_wv_kernel<<<dim3(IDIM_ / 32, HDIM_ / 32), dim3(32, 8)>>>(Wv);
    qt_kernel<<<B_, 256>>>(query, Wq, Wk);
    flash_pool_kernel<<<BS_, 256>>>(X, mask);
    epilogue_kernel<<<BS_ / MT_, 256>>>(out);
}

// round 6
// speedup vs baseline: 1.3093x; 1.2195x over previous
#include <cuda_runtime.h>
#include <cstdint>

// Shapes (fixed)
#define B_    64
#define S_    16
#define J_    256
#define QDIM_ 512
#define IDIM_ 512
#define HDIM_ 256
#define BS_   (B_ * S_)    // 1024
#define CHK_  8            // rows per staged chunk
#define NCHK_ (J_ / CHK_)  // 32 chunks

// Scratch (__device__ globals: allocation-free rule). 16B-aligned: accessed as float4/float2.
__device__ __align__(16) float g_qt[B_ * IDIM_];       // scale * Wk^T (Wq q)   [64, 512]
__device__ __align__(16) float g_pooled[BS_ * IDIM_];  // softmax-pooled inputs [1024, 512]
__device__ __align__(16) float g_WvT[IDIM_ * HDIM_];   // Wv transposed         [512, 256]
__device__ int g_mask_u8;                              // 1 = u8 bool mask, 0 = int32

// ---------------- cp.async helpers ----------------
__device__ __forceinline__ void cp_async16(unsigned dst_smem, const void* src) {
    asm volatile("cp.async.cg.shared.global [%0], [%1], 16;"
                 :: "r"(dst_smem), "l"(src));
}
__device__ __forceinline__ void cp_commit() {
    asm volatile("cp.async.commit_group;");
}
__device__ __forceinline__ void cp_wait_all() {
    asm volatile("cp.async.wait_group 0;");
}

// ---------------------------------------------------------------------------
// Kernel 1 (fused prologue), grid = 192, block = 256:
//   blocks 0..127  : transpose Wv -> g_WvT (block 0 also detects mask dtype)
//   blocks 128..191: qt_b = scale * Wk^T (Wq query_b)
// All float4-accessed shared arrays are explicitly 16B-aligned (R5 crash fix).
// ---------------------------------------------------------------------------
__global__ __launch_bounds__(256) void prologue_kernel(
    const float*    __restrict__ query,  // [64, 512]
    const float*    __restrict__ Wq,     // [256, 512]
    const float*    __restrict__ Wk,     // [256, 512]
    const float*    __restrict__ Wv,     // [256, 512]
    const unsigned* __restrict__ mask_words)
{
    const int bx  = blockIdx.x;
    const int tid = threadIdx.x;

    if (bx < 128) {
        // ---- mask dtype detection (block 0 only) ----
        if (bx == 0) {
            __shared__ int flag;
            if (tid == 0) flag = 0;
            __syncthreads();
            int loc = 0;
            #pragma unroll
            for (int k = 0; k < 4; ++k)
                if (mask_words[tid + 256 * k] > 1u) loc = 1;
            if (loc) flag = 1;
            __syncthreads();
            if (tid == 0) g_mask_u8 = flag;
        }
        // ---- Wv transpose tile ----
        __shared__ __align__(16) float tile[32][33];
        const int i0 = (bx & 15) * 32;   // IDIM tile
        const int h0 = (bx >> 4) * 32;   // HDIM tile
        const int tx = tid & 31;
        const int ty = tid >> 5;         // 0..7
        #pragma unroll
        for (int r = 0; r < 32; r += 8)
            tile[ty + r][tx] = Wv[(size_t)(h0 + ty + r) * IDIM_ + i0 + tx];
        __syncthreads();
        #pragma unroll
        for (int r = 0; r < 32; r += 8)
            g_WvT[(size_t)(i0 + ty + r) * HDIM_ + h0 + tx] = tile[tx][ty + r];
    } else {
        // ---- qt for batch b ----
        const int b = bx - 128;
        __shared__ __align__(16) float sq[QDIM_];
        __shared__ __align__(16) float sQ[HDIM_];

        sq[tid]       = query[b * QDIM_ + tid];
        sq[tid + 256] = query[b * QDIM_ + tid + 256];
        __syncthreads();

        {   // Q[b,h], thread = h
            const float4* wq = reinterpret_cast<const float4*>(Wq + (size_t)tid * QDIM_);
            const float4* q4 = reinterpret_cast<const float4*>(sq);
            float a0 = 0.f, a1 = 0.f;
            #pragma unroll 8
            for (int k = 0; k < QDIM_ / 4; k += 2) {
                float4 w = wq[k],    q  = q4[k];
                float4 w2 = wq[k+1], q2 = q4[k+1];
                a0 = fmaf(w.x,  q.x,  a0); a0 = fmaf(w.y,  q.y,  a0);
                a0 = fmaf(w.z,  q.z,  a0); a0 = fmaf(w.w,  q.w,  a0);
                a1 = fmaf(w2.x, q2.x, a1); a1 = fmaf(w2.y, q2.y, a1);
                a1 = fmaf(w2.z, q2.z, a1); a1 = fmaf(w2.w, q2.w, a1);
            }
            sQ[tid] = a0 + a1;
        }
        __syncthreads();

        const float scale = 0.0625f;  // 1/sqrt(256)
        for (int i = tid; i < IDIM_; i += 256) {
            float a0 = 0.f, a1 = 0.f, a2 = 0.f, a3 = 0.f;
            #pragma unroll 4
            for (int h = 0; h < HDIM_; h += 4) {
                a0 = fmaf(sQ[h + 0], Wk[(size_t)(h + 0) * IDIM_ + i], a0);
                a1 = fmaf(sQ[h + 1], Wk[(size_t)(h + 1) * IDIM_ + i], a1);
                a2 = fmaf(sQ[h + 2], Wk[(size_t)(h + 2) * IDIM_ + i], a2);
                a3 = fmaf(sQ[h + 3], Wk[(size_t)(h + 3) * IDIM_ + i], a3);
            }
            g_qt[b * IDIM_ + i] = ((a0 + a1) + (a2 + a3)) * scale;
        }
    }
}

// ---------------------------------------------------------------------------
// Kernel 2: chunked flash softmax-pooling, cp.async double-buffered.
// CHK=8 rows/chunk (2x16KB smem) + <=64 regs -> 4 CTAs/SM.
// One block per (b,s); warp w scores row w; coefs computed per-warp.
// ---------------------------------------------------------------------------
__global__ __launch_bounds__(256, 4) void flash_pool_kernel(
    const float* __restrict__ X,     // [64,16,256,512]
    const void*  __restrict__ mask)  // [64,16,256] u8 or i32
{
    const int bs   = blockIdx.x;
    const int b    = bs >> 4;
    const int tid  = threadIdx.x;
    const int wid  = tid >> 5;
    const int lane = tid & 31;

    __shared__ __align__(16) float4 s_stage[2][CHK_ * 128];  // 2 x 16 KB
    __shared__ float s_score[CHK_];

    const float4* x4 = reinterpret_cast<const float4*>(X + (size_t)bs * J_ * IDIM_);
    const int mask_is_u8 = g_mask_u8;
    const uint8_t* mk8  = (const uint8_t*)mask + (size_t)bs * J_;
    const int*     mk32 = (const int*)mask + (size_t)bs * J_;

    // Lane-resident q-tilde slice
    float4 qv[4];
    {
        const float4* q4 = reinterpret_cast<const float4*>(g_qt + b * IDIM_);
        #pragma unroll
        for (int k = 0; k < 4; ++k) qv[k] = q4[lane + 32 * k];
    }

    const unsigned sbuf[2] = {
        (unsigned)__cvta_generic_to_shared(&s_stage[0][0]),
        (unsigned)__cvta_generic_to_shared(&s_stage[1][0])
    };

    // Kick off chunk 0 copy (8 rows = 1024 float4; 4 per thread)
    #pragma unroll
    for (int u = 0; u < 4; ++u)
        cp_async16(sbuf[0] + (unsigned)(tid + 256 * u) * 16u, x4 + tid + 256 * u);
    cp_commit();

    float m = -1e30f, d = 0.f;
    float px = 0.f, py = 0.f;

    for (int c = 0; c < NCHK_; ++c) {
        const int cur = c & 1;

        cp_wait_all();       // this thread's copies for chunk c landed
        __syncthreads();     // all copies visible; prev chunk fully consumed

        // Issue copy for chunk c+1 into the freed buffer
        if (c < NCHK_ - 1) {
            const unsigned sb = sbuf[cur ^ 1];
            const float4* src = x4 + (size_t)(c + 1) * (CHK_ * 128);
            #pragma unroll
            for (int u = 0; u < 4; ++u)
                cp_async16(sb + (unsigned)(tid + 256 * u) * 16u, src + tid + 256 * u);
            cp_commit();
        }

        // Scores: warp w computes row w (row = 128 float4 = 4 per lane)
        {
            const float4* r0 = &s_stage[cur][wid * 128];
            float s0 = 0.f;
            #pragma unroll
            for (int k = 0; k < 4; ++k) {
                const float4 a = r0[lane + 32 * k];
                s0 = fmaf(a.x, qv[k].x, s0);
                s0 = fmaf(a.y, qv[k].y, s0);
                s0 = fmaf(a.z, qv[k].z, s0);
                s0 = fmaf(a.w, qv[k].w, s0);
            }
            #pragma unroll
            for (int off = 16; off > 0; off >>= 1)
                s0 += __shfl_xor_sync(0xffffffffu, s0, off);
            if (lane == 0) s_score[wid] = s0;
        }
        __syncthreads();

        // Every warp redundantly computes identical softmax coefficients
        float sc = -1e30f;
        if (lane < CHK_) {
            sc = s_score[lane];
            const int j = c * CHK_ + lane;
            const bool msk = mask_is_u8 ? (mk8[j] != 0) : (mk32[j] != 0);
            if (msk) sc = -1e30f;
        }
        float mx = sc;
        #pragma unroll
        for (int off = 16; off > 0; off >>= 1)
            mx = fmaxf(mx, __shfl_xor_sync(0xffffffffu, mx, off));
        const float Mn = fmaxf(m, mx);
        const float w  = (lane < CHK_) ? __expf(sc - Mn) : 0.f;
        float ws = w;
        #pragma unroll
        for (int off = 16; off > 0; off >>= 1)
            ws += __shfl_xor_sync(0xffffffffu, ws, off);
        const float f = __expf(m - Mn);
        m = Mn;
        d = fmaf(d, f, ws);

        // Accumulate: thread owns cols {2*tid, 2*tid+1}; weights via shfl
        px *= f;  py *= f;
        const float2* st2 = reinterpret_cast<const float2*>(&s_stage[cur][0]);
        #pragma unroll
        for (int r = 0; r < CHK_; ++r) {
            const float  wr = __shfl_sync(0xffffffffu, w, r);
            const float2 xv = st2[r * 256 + tid];
            px = fmaf(wr, xv.x, px);
            py = fmaf(wr, xv.y, py);
        }
        // next iteration's top barrier orders buffer reuse
    }

    const float inv = 1.f / d;
    reinterpret_cast<float2*>(g_pooled + (size_t)bs * IDIM_)[tid] =
        make_float2(px * inv, py * inv);
}

// ---------------------------------------------------------------------------
// Kernel 3: out[m, h] = sum_i pooled[m, i] * WvT[i, h]
// grid = 128 (MT=8 rows each); 256 threads = 64 h-quads x 4 m-pairs.
// ---------------------------------------------------------------------------
#define MT_ 8
__global__ __launch_bounds__(256) void epilogue_kernel(float* __restrict__ out)
{
    const int m0  = blockIdx.x * MT_;
    const int tid = threadIdx.x;
    const int hq  = tid & 63;    // h-quad: h = 4*hq .. 4*hq+3
    const int mg  = tid >> 6;    // m-pair: m = m0+2mg, m0+2mg+1

    __shared__ __align__(16) float sP[MT_][IDIM_];   // 16 KB
    {
        const float4* src = reinterpret_cast<const float4*>(g_pooled + (size_t)m0 * IDIM_);
        float4* dst = reinterpret_cast<float4*>(&sP[0][0]);
        #pragma unroll
        for (int u = 0; u < 4; ++u) dst[tid + 256 * u] = src[tid + 256 * u];
    }
    __syncthreads();

    const float4* wv4 = reinterpret_cast<const float4*>(g_WvT);
    const int mA = 2 * mg, mB = mA + 1;
    float4 a0 = make_float4(0.f, 0.f, 0.f, 0.f);
    float4 a1 = make_float4(0.f, 0.f, 0.f, 0.f);

    #pragma unroll 8
    for (int i = 0; i < IDIM_; ++i) {
        const float4 w  = __ldg(&wv4[i * 64 + hq]);
        const float  pA = sP[mA][i];
        const float  pB = sP[mB][i];
        a0.x = fmaf(w.x, pA, a0.x);  a0.y = fmaf(w.y, pA, a0.y);
        a0.z = fmaf(w.z, pA, a0.z);  a0.w = fmaf(w.w, pA, a0.w);
        a1.x = fmaf(w.x, pB, a1.x);  a1.y = fmaf(w.y, pB, a1.y);
        a1.z = fmaf(w.z, pB, a1.z);  a1.w = fmaf(w.w, pB, a1.w);
    }

    reinterpret_cast<float4*>(out + (size_t)(m0 + mA) * HDIM_)[hq] = a0;
    reinterpret_cast<float4*>(out + (size_t)(m0 + mB) * HDIM_)[hq] = a1;
}

// ---------------------------------------------------------------------------
// Launch.  Inputs: query, other_semesters, mask, Wq, Wk, Wv
// ---------------------------------------------------------------------------
extern "C" void kernel_launch(void* const* d_in, const int* in_sizes, int n_in,
                              void* d_out, int out_size)
{
    const float* query = (const float*)d_in[0];
    const float* X     = (const float*)d_in[1];
    const void*  mask  = d_in[2];
    const float* Wq    = (const float*)d_in[3];
    const float* Wk    = (const float*)d_in[4];
    const float* Wv    = (const float*)d_in[5];
    float*       out   = (float*)d_out;

    prologue_kernel<<<192, 256>>>(query, Wq, Wk, Wv, (const unsigned*)mask);
    flash_pool_kernel<<<BS_, 256>>>(X, mask);
    epilogue_kernel<<<BS_ / MT_, 256>>>(out);
}